// round 6
// baseline (speedup 1.0000x reference)
#include <cuda_runtime.h>
#include <math.h>

#define D        1024
#define PD       32
#define NPAT     256
#define TOPK     4
#define NTOK_MAX 2048
#define CAP      2048          // worst case: every token picks this pattern
#define TB       32            // tokens per expert tile
#define ETHREADS 512
#define RTOKS    8             // tokens per route CTA

// ---------------- scratch (__device__ globals: allocation-free) ----------------
__device__ int   g_counts[NPAT];
__device__ int   g_lists[NPAT * CAP];                       // entry = tok*4 + k
__device__ float g_wts[NTOK_MAX * TOPK];                    // softmax weight * scale
__device__ float g_part[(size_t)NTOK_MAX * TOPK * D];       // 32 MB partials

// ---------------- kernel 0: zero counts ----------------
__global__ void zero_counts_kernel() { g_counts[threadIdx.x] = 0; }

// ---------------- kernel 1: routing (hash -> sim -> top4 -> softmax -> append) ----------------
__global__ __launch_bounds__(256) void route_kernel(
    const float* __restrict__ x,
    const float* __restrict__ hw,     // [PD, D]
    const float* __restrict__ keys,   // [NPAT, PD]
    const float* __restrict__ scale)
{
    __shared__ float xs[RTOKS * D];         // 32 KB
    __shared__ float h[RTOKS][PD];
    __shared__ float sims[RTOKS][NPAT];     // 8 KB
    __shared__ float sc_s;

    const int tid  = threadIdx.x;
    const int lane = tid & 31;
    const int w    = tid >> 5;
    const int tok0 = blockIdx.x * RTOKS;

    // stage 8 tokens of x
    const float4* xg4 = reinterpret_cast<const float4*>(x) + (size_t)tok0 * (D / 4);
    float4* xs4 = reinterpret_cast<float4*>(xs);
    #pragma unroll
    for (int i = 0; i < RTOKS; i++) xs4[i * 256 + tid] = xg4[i * 256 + tid];
    if (tid == 0) sc_s = scale[0];
    __syncthreads();

    // hash: warp w computes h[t][j] for j = 4w..4w+3, all 8 tokens.
    // hw rows read once per CTA (each row owned by exactly one warp).
    {
        const float4* hw4 = reinterpret_cast<const float4*>(hw);
        #pragma unroll
        for (int jj = 0; jj < 4; jj++) {
            const int j = w * 4 + jj;
            float acc[RTOKS];
            #pragma unroll
            for (int t = 0; t < RTOKS; t++) acc[t] = 0.f;
            #pragma unroll
            for (int i = 0; i < 8; i++) {
                const float4 hv = hw4[j * (D / 4) + lane + 32 * i];
                #pragma unroll
                for (int t = 0; t < RTOKS; t++) {
                    const float4 xv = xs4[t * 256 + lane + 32 * i];
                    acc[t] += hv.x * xv.x + hv.y * xv.y + hv.z * xv.z + hv.w * xv.w;
                }
            }
            #pragma unroll
            for (int t = 0; t < RTOKS; t++) {
                float a = acc[t];
                #pragma unroll
                for (int off = 16; off; off >>= 1)
                    a += __shfl_xor_sync(0xFFFFFFFFu, a, off);
                if (lane == 0) h[t][j] = a;
            }
        }
    }
    __syncthreads();

    // sims: thread = pattern, loops 8 tokens
    {
        float kreg[PD];
        const float4* k4 = reinterpret_cast<const float4*>(keys) + tid * (PD / 4);
        #pragma unroll
        for (int i = 0; i < PD / 4; i++) {
            const float4 v = k4[i];
            kreg[4 * i] = v.x; kreg[4 * i + 1] = v.y;
            kreg[4 * i + 2] = v.z; kreg[4 * i + 3] = v.w;
        }
        #pragma unroll
        for (int t = 0; t < RTOKS; t++) {
            float s = 0.f;
            #pragma unroll
            for (int i = 0; i < PD; i++) s += kreg[i] * h[t][i];
            sims[t][tid] = s;
        }
    }
    __syncthreads();

    // top-4 + softmax per token (warp w owns token w); ties -> lower index
    {
        float kval[TOPK]; int kidx[TOPK];
        for (int k = 0; k < TOPK; k++) {
            float bv = -1e30f; int bi = 0;
            #pragma unroll
            for (int t2 = 0; t2 < 8; t2++) {
                const int n = lane * 8 + t2;
                const float v = sims[w][n];
                if (v > bv) { bv = v; bi = n; }
            }
            #pragma unroll
            for (int off = 16; off; off >>= 1) {
                const float ov = __shfl_xor_sync(0xFFFFFFFFu, bv, off);
                const int   oi = __shfl_xor_sync(0xFFFFFFFFu, bi, off);
                if (ov > bv || (ov == bv && oi < bi)) { bv = ov; bi = oi; }
            }
            if (lane == 0) { kval[k] = bv; kidx[k] = bi; sims[w][bi] = -1e30f; }
            __syncwarp();
        }
        if (lane == 0) {
            const int gtok = tok0 + w;
            const float m = kval[0];
            float e[TOPK]; float ssum = 0.f;
            #pragma unroll
            for (int k = 0; k < TOPK; k++) { e[k] = expf(kval[k] - m); ssum += e[k]; }
            const float sc = sc_s / ssum;
            #pragma unroll
            for (int k = 0; k < TOPK; k++) {
                const int p = kidx[k];
                const int entry = gtok * TOPK + k;
                g_wts[entry] = e[k] * sc;
                const int slot = atomicAdd(&g_counts[p], 1);
                g_lists[p * CAP + slot] = entry;
            }
        }
    }
}

// ---------------- kernel 2: per-pattern expert (down -> silu -> up) ----------------
// smem floats: xs 32768 | vds 4096 | proj 1024 | wts 32 | ents 32(int)
#define SM_XS   0
#define SM_VDS  (TB * D)                  // 32768
#define SM_PROJ (SM_VDS + 128 * PD)       // +4096
#define SM_WTS  (SM_PROJ + TB * PD)       // +1024
#define SM_ENT  (SM_WTS + TB)             // +32
#define EXPERT_SMEM_BYTES ((SM_ENT + TB) * 4)

__global__ __launch_bounds__(ETHREADS, 1) void expert_kernel(
    const float* __restrict__ x,
    const float* __restrict__ vd,     // [NPAT, D, PD]
    const float* __restrict__ vu)     // [NPAT, PD, D]
{
    extern __shared__ float sm[];
    float* xs   = sm + SM_XS;
    float* vds  = sm + SM_VDS;
    float* proj = sm + SM_PROJ;
    float* wts  = sm + SM_WTS;
    int*   ents = reinterpret_cast<int*>(sm + SM_ENT);
    __shared__ int n_s;

    const int p   = blockIdx.x;
    const int tid = threadIdx.x;
    if (tid == 0) n_s = g_counts[p];
    __syncthreads();
    const int n = n_s;
    if (n == 0) return;

    const float4* vdg4 = reinterpret_cast<const float4*>(vd + (size_t)p * D * PD);
    const float2* vug2 = reinterpret_cast<const float2*>(vu + (size_t)p * PD * D);
    const float4* xg4  = reinterpret_cast<const float4*>(x);

    const int t  = tid >> 4;     // 0..31 token slot
    const int j2 = tid & 15;     // float2 over PD

    for (int base = 0; base < n; base += TB) {
        const int nt = min(TB, n - base);

        if (tid < TB) {
            if (tid < nt) {
                const int e = g_lists[p * CAP + base + tid];
                ents[tid] = e; wts[tid] = g_wts[e];
            } else { ents[tid] = 0; wts[tid] = 0.f; }
        }
        __syncthreads();

        // stage x tile (zeros for padded slots)
        float4* xs4 = reinterpret_cast<float4*>(xs);
        #pragma unroll
        for (int i = 0; i < 16; i++) {
            const int idx = tid + i * ETHREADS;   // 0..8191
            const int tt = idx >> 8, col = idx & 255;
            float4 v = make_float4(0.f, 0.f, 0.f, 0.f);
            if (tt < nt) v = xg4[(size_t)(ents[tt] >> 2) * 256 + col];
            xs4[tt * 256 + col] = v;
        }
        __syncthreads();

        // ---- down: proj[t][j] = sum_d xs[t][d] * vd[d][j]
        float accx = 0.f, accy = 0.f;
        float4* vds4 = reinterpret_cast<float4*>(vds);
        for (int dc = 0; dc < 8; dc++) {
            vds4[tid]       = vdg4[dc * 1024 + tid];
            vds4[tid + 512] = vdg4[dc * 1024 + tid + 512];
            __syncthreads();
            const float*  xrow = xs + t * D + dc * 128;
            const float2* vrow = reinterpret_cast<const float2*>(vds) + j2;
            #pragma unroll 16
            for (int dd = 0; dd < 128; dd++) {
                const float  xv = xrow[dd];
                const float2 v  = vrow[dd * 16];
                accx += xv * v.x; accy += xv * v.y;
            }
            __syncthreads();
        }
        // silu * (softmax weight * scale)
        {
            const float wt = wts[t];
            proj[t * PD + 2 * j2]     = accx / (1.f + expf(-accx)) * wt;
            proj[t * PD + 2 * j2 + 1] = accy / (1.f + expf(-accy)) * wt;
        }
        __syncthreads();

        // ---- up: part[t][d] = sum_j proj[t][j] * vu[j][d]; thread owns float2 of d
        float2 acc[TB];
        #pragma unroll
        for (int tt = 0; tt < TB; tt++) acc[tt] = make_float2(0.f, 0.f);
        #pragma unroll 2
        for (int j = 0; j < PD; j++) {
            const float2 v = vug2[j * (D / 2) + tid];
            #pragma unroll
            for (int tt = 0; tt < TB; tt++) {
                const float pj = proj[tt * PD + j];
                acc[tt].x += pj * v.x; acc[tt].y += pj * v.y;
            }
        }
        #pragma unroll
        for (int tt = 0; tt < TB; tt++) {
            if (tt < nt) {
                float2* pp = reinterpret_cast<float2*>(g_part + (size_t)ents[tt] * D);
                pp[tid] = acc[tt];
            }
        }
        __syncthreads();   // protect smem before next tile
    }
}

// ---------------- kernel 3: gather out = x + sum_k partial ----------------
__global__ __launch_bounds__(256) void gather_kernel(
    const float* __restrict__ x, float* __restrict__ out)
{
    const int tok = blockIdx.x, tid = threadIdx.x;
    const float4* xg4 = reinterpret_cast<const float4*>(x) + (size_t)tok * 256;
    float4 o = xg4[tid];
    const float4* p4 = reinterpret_cast<const float4*>(g_part) + (size_t)tok * TOPK * 256;
    #pragma unroll
    for (int k = 0; k < TOPK; k++) {
        const float4 v = p4[k * 256 + tid];
        o.x += v.x; o.y += v.y; o.z += v.z; o.w += v.w;
    }
    reinterpret_cast<float4*>(out)[(size_t)tok * 256 + tid] = o;
}

// ---------------- launcher ----------------
extern "C" void kernel_launch(void* const* d_in, const int* in_sizes, int n_in,
                              void* d_out, int out_size) {
    const float* x     = (const float*)d_in[0];
    const float* hw    = (const float*)d_in[1];
    const float* keys  = (const float*)d_in[2];
    const float* vd    = (const float*)d_in[3];
    const float* vu    = (const float*)d_in[4];
    const float* scale = (const float*)d_in[5];
    float* out = (float*)d_out;

    const int ntok = in_sizes[0] / D;   // 2048

    zero_counts_kernel<<<1, NPAT>>>();
    route_kernel<<<ntok / RTOKS, 256>>>(x, hw, keys, scale);
    cudaFuncSetAttribute(expert_kernel, cudaFuncAttributeMaxDynamicSharedMemorySize,
                         EXPERT_SMEM_BYTES);
    expert_kernel<<<NPAT, ETHREADS, EXPERT_SMEM_BYTES>>>(x, vd, vu);
    gather_kernel<<<ntok, 256>>>(x, out);
}